// round 12
// baseline (speedup 1.0000x reference)
#include <cuda_runtime.h>
#include <cstdint>

#define RES   64
#define CH    8
#define NB    64
#define CORE  32
#define POS   16
#define DIMSZ (CORE*CORE*CORE*CH)   // 262144
#define BATCH 32

// ---- GEMM geometry (R11-proven inner structure) ----
#define DPB   256                          // dims per gemm block
#define CBLK  (DIMSZ / DPB)                // 1024 gemm blocks
#define SMEM_U_BYTES (DPB * NB * 4)        // 64 KB U tile
#define SMEM_Z_BYTES (NB * BATCH * 8)      // 16 KB packed zL
#define SMEM_TOTAL   (SMEM_U_BYTES + SMEM_Z_BYTES)   // 80 KB dynamic

// ---- zero geometry (R10-proven path) ----
#define F4_TOTAL  (BATCH*CH*RES*RES*RES/4) // 16,777,216 float4
#define F4_PER_TH 8
#define ZBLK (F4_TOTAL / (256 * F4_PER_TH))  // 8192 zero blocks

#define GRID (CBLK + ZBLK)                 // 9216 = 9 * 1024

#define FMA2(a, u, s) asm("fma.rn.f32x2 %0, %1, %2, %0;" : "+l"(a) : "l"(u), "l"(s))

// Single fused kernel. Dispatch-order interleave: every 9th block is a GEMM
// block, the rest are zero blocks -> each SM holds a mix of (smem-GEMM) and
// (pure write-stream) CTAs for the WHOLE kernel, so U reads, core writes and
// periphery zero writes share DRAM continuously instead of serializing.
__global__ void __launch_bounds__(256, 2) core_subspace_fused(
    const float* __restrict__ z,   // (32, 64)
    const float* __restrict__ U,   // (64, 262144)
    const float* __restrict__ L,   // (64,)
    const float* __restrict__ mu,  // (262144,)
    float* __restrict__ out)       // (32, 8, 64, 64, 64)
{
    const int tid = threadIdx.x;
    const int bid = blockIdx.x;
    const int g9  = bid / 9;
    const int r9  = bid - g9 * 9;

    if (r9 != 0) {
        // ---------------- periphery zero-fill (R10-proven) ----------------
        const int zb = g9 * 8 + (r9 - 1);            // 0..8191
        const float4 zero4 = make_float4(0.f, 0.f, 0.f, 0.f);
        float4* o4 = reinterpret_cast<float4*>(out);
#pragma unroll
        for (int c = 0; c < F4_PER_TH; c++) {
            const int f = zb * (256 * F4_PER_TH) + c * 256 + tid;
            const unsigned w4 = f & 15;
            const unsigned j  = (f >> 4)  & 63;
            const unsigned i  = (f >> 10) & 63;
            const bool in_core = (i - 16u < 32u) & (j - 16u < 32u) & (w4 - 4u < 8u);
            if (!in_core) __stcs(&o4[f], zero4);     // core written by gemm blocks
        }
        return;
    }

    // ---------------- smem-tiled GEMM (R11-proven) ----------------
    extern __shared__ char smem[];
    float* su = reinterpret_cast<float*>(smem);                      // [NB][DPB]
    unsigned long long* szb =
        reinterpret_cast<unsigned long long*>(smem + SMEM_U_BYTES);  // [NB][BATCH]

    const int D0 = g9 * DPB;                          // gemm block id = g9

    // zL packed duplicated-f32x2, layout [k][batch].
    for (int idx = tid; idx < NB * BATCH; idx += 256) {
        const int b = idx & 31;
        const int k = idx >> 5;
        float v = L[k] * z[b * NB + k];
        unsigned int vb = __float_as_uint(v);
        unsigned long long p;
        asm("mov.b64 %0, {%1, %1};" : "=l"(p) : "r"(vb));
        szb[k * BATCH + b] = p;
    }

    // Stage U tile: 64 rows x 256 floats = 4096 float4, 16 per thread.
#pragma unroll
    for (int i = 0; i < 16; i++) {
        const int idx = i * 256 + tid;
        const int k   = idx >> 6;
        const int c4  = idx & 63;
        const float4 v = *reinterpret_cast<const float4*>(
            U + (size_t)k * DIMSZ + D0 + c4 * 4);
        *reinterpret_cast<float4*>(&su[k * DPB + c4 * 4]) = v;
    }
    __syncthreads();

    const int g  = tid >> 6;         // batch group 0..3 (8 batches each)
    const int q  = tid & 63;         // dim-quad 0..63
    const int b0 = g * 8;
    const int d0 = D0 + q * 4;

    const ulonglong2 mu2 = *reinterpret_cast<const ulonglong2*>(mu + d0);

    unsigned long long acc[8][2];    // 32 registers
#pragma unroll
    for (int bb = 0; bb < 8; bb++) { acc[bb][0] = mu2.x; acc[bb][1] = mu2.y; }

#pragma unroll 4
    for (int k = 0; k < NB; k++) {
        const ulonglong2 ud = *reinterpret_cast<const ulonglong2*>(
            &su[k * DPB + q * 4]);                       // LDS.128, conflict-free
        const ulonglong2* zp = reinterpret_cast<const ulonglong2*>(
            &szb[k * BATCH + b0]);
        const ulonglong2 z01 = zp[0];                    // LDS.128 broadcast x4
        const ulonglong2 z23 = zp[1];
        const ulonglong2 z45 = zp[2];
        const ulonglong2 z67 = zp[3];

        FMA2(acc[0][0], ud.x, z01.x); FMA2(acc[0][1], ud.y, z01.x);
        FMA2(acc[1][0], ud.x, z01.y); FMA2(acc[1][1], ud.y, z01.y);
        FMA2(acc[2][0], ud.x, z23.x); FMA2(acc[2][1], ud.y, z23.x);
        FMA2(acc[3][0], ud.x, z23.y); FMA2(acc[3][1], ud.y, z23.y);
        FMA2(acc[4][0], ud.x, z45.x); FMA2(acc[4][1], ud.y, z45.x);
        FMA2(acc[5][0], ud.x, z45.y); FMA2(acc[5][1], ud.y, z45.y);
        FMA2(acc[6][0], ud.x, z67.x); FMA2(acc[6][1], ud.y, z67.x);
        FMA2(acc[7][0], ud.x, z67.y); FMA2(acc[7][1], ud.y, z67.y);
    }

    // Scatter 4-dim chunk into the core for this thread's 8 batches.
    const int w = d0 & 31;
    const int j = (d0 >> 5) & 31;
    const int i = (d0 >> 10) & 31;
    const int c = d0 >> 15;

    const size_t obase = (size_t)c * (RES * RES * RES)
                       + (size_t)(i + POS) * (RES * RES)
                       + (size_t)(j + POS) * RES
                       + (size_t)(w + POS);

#pragma unroll
    for (int bb = 0; bb < 8; bb++) {
        float* o = out + (size_t)(b0 + bb) * (CH * RES * RES * RES) + obase;
        float4 v;
        v.x = __uint_as_float((unsigned)(acc[bb][0]));
        v.y = __uint_as_float((unsigned)(acc[bb][0] >> 32));
        v.z = __uint_as_float((unsigned)(acc[bb][1]));
        v.w = __uint_as_float((unsigned)(acc[bb][1] >> 32));
        __stcs(reinterpret_cast<float4*>(o), v);
    }
}

extern "C" void kernel_launch(void* const* d_in, const int* in_sizes, int n_in,
                              void* d_out, int out_size)
{
    const float* z  = (const float*)d_in[0];
    const float* U  = (const float*)d_in[1];
    const float* L  = (const float*)d_in[2];
    const float* mu = (const float*)d_in[3];
    float* out = (float*)d_out;

    static bool attr_set = false;
    if (!attr_set) {
        cudaFuncSetAttribute(core_subspace_fused,
                             cudaFuncAttributeMaxDynamicSharedMemorySize,
                             SMEM_TOTAL);
        attr_set = true;
    }

    core_subspace_fused<<<GRID, 256, SMEM_TOTAL>>>(z, U, L, mu, out);
}